// round 4
// baseline (speedup 1.0000x reference)
#include <cuda_runtime.h>
#include <cstddef>

#define HW   4096
#define Dh   128
#define Cc   256
#define NB   4

typedef unsigned long long ull;

// ---- packed f32x2 helpers (sm_103a FFMA2 — only reachable via PTX) ----
__device__ __forceinline__ ull dup2(float x) {
  ull r; asm("mov.b64 %0, {%1, %1};" : "=l"(r) : "f"(x)); return r;
}
__device__ __forceinline__ void fma2(ull& d, ull a, ull b) {
  asm("fma.rn.f32x2 %0, %1, %2, %3;" : "=l"(d) : "l"(a), "l"(b), "l"(d));
}
__device__ __forceinline__ void mul2(ull& d, ull a, ull b) {
  asm("mul.rn.f32x2 %0, %1, %2;" : "=l"(d) : "l"(a), "l"(b));
}
__device__ __forceinline__ void unpack2(ull v, float& lo, float& hi) {
  asm("mov.b64 {%0, %1}, %2;" : "=f"(lo), "=f"(hi) : "l"(v));
}

// ---------------- scratch (device globals, no allocation) ----------------
__device__ float d_theta[2*NB*HW*Dh];   // [side][b][q][d]
__device__ float d_phi  [2*NB*Dh*HW];   // [side][b][d][k]
__device__ float d_g    [2*NB*HW*Dh];   // [side][b][k][d]
__device__ float d_after[2*NB*HW*Dh];   // [side][b][q][d]
__device__ float d_y    [2*NB*Cc*HW];   // [side][b][c][q]
__device__ float2 d_bn  [2*Cc];         // (mean, invstd)

// ======================= projection kernel (theta/phi/g) =======================
// grid (64 qtiles, B, 6 = side*3+proj), 256 threads, smem 51200B
__global__ __launch_bounds__(256) void proj_kernel(
    const float* __restrict__ left,   const float* __restrict__ right,
    const float* __restrict__ pre_l,  const float* __restrict__ pre_r,
    const float* __restrict__ query_l,const float* __restrict__ key_l,
    const float* __restrict__ query_r,const float* __restrict__ key_r,
    const float* __restrict__ theta_w,const float* __restrict__ theta_b,
    const float* __restrict__ phi_w,  const float* __restrict__ phi_b,
    const float* __restrict__ g_w,    const float* __restrict__ g_b)
{
  extern __shared__ float sm[];
  float* Xs = sm;            // [64 c][68]  (x tile, q contiguous)
  float* Wt = sm + 64*68;    // [64 c][132] (W^T tile, d contiguous)

  const int qt = blockIdx.x, b = blockIdx.y, z = blockIdx.z;
  const int side = z / 3, proj = z - side*3;

  const float* src; const float* w; const float* bias; int cin;
  if (proj == 0)      { src = side ? right : left;  w = theta_w; bias = theta_b; cin = 257; }
  else if (proj == 1) { src = side ? left  : right; w = phi_w;   bias = phi_b;   cin = 256; }
  else                { src = side ? left  : right; w = g_w;     bias = g_b;     cin = 256; }

  const int tid = threadIdx.x, tx = tid & 15, ty = tid >> 4;
  const int q0 = qt * 64;
  const float* xb = src + (size_t)b * Cc * HW;

  ull acc2[4][4];
  #pragma unroll
  for (int i = 0; i < 4; i++)
    #pragma unroll
    for (int j = 0; j < 4; j++) acc2[i][j] = 0ull;

  for (int c0 = 0; c0 < 256; c0 += 64) {
    __syncthreads();
    for (int i = tid; i < 64*16; i += 256) {
      int r = i >> 4, c4 = (i & 15) * 4;
      *(float4*)&Xs[r*68 + c4] = *(const float4*)&xb[(size_t)(c0 + r)*HW + q0 + c4];
    }
    for (int i = tid; i < 128*64; i += 256) {
      int d = i >> 6, c = i & 63;
      Wt[c*132 + d] = w[d*cin + c0 + c];
    }
    __syncthreads();
    #pragma unroll 4
    for (int c = 0; c < 64; c++) {
      float4 q4 = *(const float4*)&Xs[c*68 + ty*4];
      ulonglong2 w0 = *(const ulonglong2*)&Wt[c*132 + tx*8];
      ulonglong2 w1 = *(const ulonglong2*)&Wt[c*132 + tx*8 + 4];
      ull wv2[4] = {w0.x, w0.y, w1.x, w1.y};
      float qv[4] = {q4.x, q4.y, q4.z, q4.w};
      #pragma unroll
      for (int qq = 0; qq < 4; qq++) {
        ull qd = dup2(qv[qq]);
        #pragma unroll
        for (int p = 0; p < 4; p++) fma2(acc2[qq][p], qd, wv2[p]);
      }
    }
  }

  float acc[4][8];
  #pragma unroll
  for (int qq = 0; qq < 4; qq++)
    #pragma unroll
    for (int p = 0; p < 4; p++)
      unpack2(acc2[qq][p], acc[qq][2*p], acc[qq][2*p+1]);

  const int d0 = tx*8;
  const int sb = side*NB + b;
  float outv[4][8];

  if (proj == 0) {
    const float* pre = side ? pre_r : pre_l;
    const float* qry = side ? query_r : query_l;
    float prev[4];
    #pragma unroll
    for (int qq = 0; qq < 4; qq++)
      prev[qq] = pre[(size_t)b*HW + q0 + ty*4 + qq] * (1.0f/128.0f);
    #pragma unroll
    for (int qq = 0; qq < 4; qq++) {
      int q = q0 + ty*4 + qq;
      #pragma unroll
      for (int dd = 0; dd < 8; dd++) {
        int d = d0 + dd;
        outv[qq][dd] = acc[qq][dd] + bias[d] + w[d*257 + 256]*prev[qq]
                     + qry[((size_t)b*Dh + d)*HW + q];
      }
    }
    float* dst = d_theta + (size_t)sb*HW*Dh;
    #pragma unroll
    for (int qq = 0; qq < 4; qq++) {
      size_t o = (size_t)(q0 + ty*4 + qq)*Dh + d0;
      *(float4*)&dst[o]     = make_float4(outv[qq][0],outv[qq][1],outv[qq][2],outv[qq][3]);
      *(float4*)&dst[o + 4] = make_float4(outv[qq][4],outv[qq][5],outv[qq][6],outv[qq][7]);
    }
  } else if (proj == 1) {
    const float* kf = side ? key_l : key_r;
    #pragma unroll
    for (int qq = 0; qq < 4; qq++) {
      int q = q0 + ty*4 + qq;
      #pragma unroll
      for (int dd = 0; dd < 8; dd++) {
        int d = d0 + dd;
        outv[qq][dd] = acc[qq][dd] + bias[d] + kf[((size_t)b*Dh + d)*HW + q];
      }
    }
    float* dst = d_phi + (size_t)sb*Dh*HW;
    #pragma unroll
    for (int dd = 0; dd < 8; dd++) {
      *(float4*)&dst[(size_t)(d0+dd)*HW + q0 + ty*4] =
        make_float4(outv[0][dd],outv[1][dd],outv[2][dd],outv[3][dd]);
    }
  } else {
    #pragma unroll
    for (int qq = 0; qq < 4; qq++)
      #pragma unroll
      for (int dd = 0; dd < 8; dd++)
        outv[qq][dd] = acc[qq][dd] + bias[d0+dd];
    float* dst = d_g + (size_t)sb*HW*Dh;
    #pragma unroll
    for (int qq = 0; qq < 4; qq++) {
      size_t o = (size_t)(q0 + ty*4 + qq)*Dh + d0;
      *(float4*)&dst[o]     = make_float4(outv[qq][0],outv[qq][1],outv[qq][2],outv[qq][3]);
      *(float4*)&dst[o + 4] = make_float4(outv[qq][4],outv[qq][5],outv[qq][6],outv[qq][7]);
    }
  }
}

// ======================= fused flash attention + soft-argmax =======================
// grid (64 qtiles, B, 2 sides), 256 threads, smem 119808B
__global__ __launch_bounds__(256) void flash_kernel(float* __restrict__ out)
{
  extern __shared__ float sm[];
  float* Qs = sm;                 // [64][132]
  float* Ks = Qs + 64*132;        // [128][68]  ([d][k])
  float* Gs = Ks + 128*68;        // [64][132]  ([k][d])
  float* Ps = Gs + 64*132;        // [64][68]

  const int qt = blockIdx.x, b = blockIdx.y, side = blockIdx.z;
  const int sb = side*NB + b;
  const float* Qg = d_theta + (size_t)sb*HW*Dh;
  const float* Kg = d_phi   + (size_t)sb*Dh*HW;
  const float* Gg = d_g     + (size_t)sb*HW*Dh;
  float*       Og = d_after + (size_t)sb*HW*Dh;

  const int tid = threadIdx.x, tx = tid & 15, ty = tid >> 4;
  const int q0 = qt * 64;

  for (int i = tid; i < 64*32; i += 256) {
    int r = i >> 5, c4 = (i & 31) * 4;
    *(float4*)&Qs[r*132 + c4] = *(const float4*)&Qg[(size_t)(q0+r)*Dh + c4];
  }

  float m[4], lp[4], cp[4];
  ull o2[4][4];
  #pragma unroll
  for (int qq = 0; qq < 4; qq++) {
    m[qq] = -1e30f; lp[qq] = 0.f; cp[qq] = 0.f;
    #pragma unroll
    for (int p = 0; p < 4; p++) o2[qq][p] = 0ull;
  }

  for (int kt = 0; kt < 64; kt++) {
    const int k0 = kt * 64;
    __syncthreads();
    for (int i = tid; i < 128*16; i += 256) {
      int r = i >> 4, c4 = (i & 15) * 4;
      *(float4*)&Ks[r*68 + c4] = *(const float4*)&Kg[(size_t)r*HW + k0 + c4];
    }
    for (int i = tid; i < 64*32; i += 256) {
      int r = i >> 5, c4 = (i & 31) * 4;
      *(float4*)&Gs[r*132 + c4] = *(const float4*)&Gg[(size_t)(k0+r)*Dh + c4];
    }
    __syncthreads();

    // ---- S = Q K  (64x64 tile, each thread 4q x 4k, packed along k) ----
    ull s2[4][2];
    #pragma unroll
    for (int qq = 0; qq < 4; qq++) { s2[qq][0] = 0ull; s2[qq][1] = 0ull; }

    #pragma unroll 2
    for (int d4 = 0; d4 < 32; d4++) {
      ull kv2[4][2];
      #pragma unroll
      for (int j = 0; j < 4; j++) {
        ulonglong2 t = *(const ulonglong2*)&Ks[(d4*4+j)*68 + tx*4];
        kv2[j][0] = t.x; kv2[j][1] = t.y;
      }
      #pragma unroll
      for (int qq = 0; qq < 4; qq++) {
        float4 t = *(const float4*)&Qs[(ty*4+qq)*132 + d4*4];
        float qv[4] = {t.x, t.y, t.z, t.w};
        #pragma unroll
        for (int j = 0; j < 4; j++) {
          ull qd = dup2(qv[j]);
          fma2(s2[qq][0], qd, kv2[j][0]);
          fma2(s2[qq][1], qd, kv2[j][1]);
        }
      }
    }

    float s[4][4];
    #pragma unroll
    for (int qq = 0; qq < 4; qq++) {
      unpack2(s2[qq][0], s[qq][0], s[qq][1]);
      unpack2(s2[qq][1], s[qq][2], s[qq][3]);
    }

    // ---- online softmax update ----
    float tmax[4];
    #pragma unroll
    for (int qq = 0; qq < 4; qq++)
      tmax[qq] = fmaxf(fmaxf(s[qq][0],s[qq][1]), fmaxf(s[qq][2],s[qq][3]));
    #pragma unroll
    for (int off = 8; off; off >>= 1)
      #pragma unroll
      for (int qq = 0; qq < 4; qq++)
        tmax[qq] = fmaxf(tmax[qq], __shfl_xor_sync(0xffffffffu, tmax[qq], off));

    #pragma unroll
    for (int qq = 0; qq < 4; qq++) {
      float mn  = fmaxf(m[qq], tmax[qq]);
      float scl = __expf(m[qq] - mn);
      m[qq] = mn;
      float rs = 0.f, rc = 0.f;
      #pragma unroll
      for (int kk = 0; kk < 4; kk++) {
        float p = __expf(s[qq][kk] - mn);
        s[qq][kk] = p;
        rs += p;
        rc += p * (float)((k0 + tx*4 + kk) & 127);
      }
      lp[qq] = lp[qq]*scl + rs;
      cp[qq] = cp[qq]*scl + rc;
      ull scld = dup2(scl);
      #pragma unroll
      for (int p = 0; p < 4; p++) mul2(o2[qq][p], o2[qq][p], scld);
    }

    #pragma unroll
    for (int qq = 0; qq < 4; qq++)
      *(float4*)&Ps[(ty*4+qq)*68 + tx*4] =
        make_float4(s[qq][0], s[qq][1], s[qq][2], s[qq][3]);
    __syncthreads();

    // ---- O += P G  (each thread 4q x 8d, packed along d) ----
    #pragma unroll 2
    for (int k4 = 0; k4 < 16; k4++) {
      ull gv2[4][4];
      #pragma unroll
      for (int j = 0; j < 4; j++) {
        ulonglong2 a = *(const ulonglong2*)&Gs[(k4*4+j)*132 + tx*8];
        ulonglong2 c = *(const ulonglong2*)&Gs[(k4*4+j)*132 + tx*8 + 4];
        gv2[j][0]=a.x; gv2[j][1]=a.y; gv2[j][2]=c.x; gv2[j][3]=c.y;
      }
      #pragma unroll
      for (int qq = 0; qq < 4; qq++) {
        float4 t = *(const float4*)&Ps[(ty*4+qq)*68 + k4*4];
        float pv[4] = {t.x, t.y, t.z, t.w};
        #pragma unroll
        for (int j = 0; j < 4; j++) {
          ull pd = dup2(pv[j]);
          #pragma unroll
          for (int p = 0; p < 4; p++) fma2(o2[qq][p], pd, gv2[j][p]);
        }
      }
    }
  }

  // reduce l and c across the 16 tx lanes
  #pragma unroll
  for (int off = 8; off; off >>= 1)
    #pragma unroll
    for (int qq = 0; qq < 4; qq++) {
      lp[qq] += __shfl_xor_sync(0xffffffffu, lp[qq], off);
      cp[qq] += __shfl_xor_sync(0xffffffffu, cp[qq], off);
    }

  const size_t IDX_BASE = (size_t)2*NB*Cc*HW;
  #pragma unroll
  for (int qq = 0; qq < 4; qq++) {
    float inv = 1.0f / lp[qq];
    ull invd = dup2(inv);
    int q = q0 + ty*4 + qq;
    size_t oo = (size_t)q*Dh + tx*8;
    ull r0 = o2[qq][0], r1 = o2[qq][1], r2 = o2[qq][2], r3 = o2[qq][3];
    mul2(r0, r0, invd); mul2(r1, r1, invd); mul2(r2, r2, invd); mul2(r3, r3, invd);
    ulonglong2 v0; v0.x = r0; v0.y = r1;
    ulonglong2 v1; v1.x = r2; v1.y = r3;
    *(ulonglong2*)&Og[oo]     = v0;
    *(ulonglong2*)&Og[oo + 4] = v1;
    if (tx == 0) {
      out[IDX_BASE + (size_t)side*NB*HW + (size_t)b*HW + q] =
        (float)(q & 127) - cp[qq]*inv;
    }
  }
}

// ======================= up-projection =======================
// grid (64 qtiles, B, 4 = side*2 + chalf), 256 threads, smem 101376B
__global__ __launch_bounds__(256) void up_kernel(
    const float* __restrict__ up_w, const float* __restrict__ up_b)
{
  extern __shared__ float sm[];
  float* As = sm;            // [64 q][132]
  float* Ws = sm + 64*132;   // [128 d][132]  ([d][c] transposed)

  const int qt = blockIdx.x, b = blockIdx.y, z = blockIdx.z;
  const int side = z >> 1, ch = z & 1;
  const int sb = side*NB + b;
  const float* Ap = d_after + (size_t)sb*HW*Dh;
  float*       Yp = d_y     + (size_t)sb*Cc*HW;
  const int c0 = ch*128;
  const int tid = threadIdx.x, tx = tid & 15, ty = tid >> 4;
  const int q0 = qt*64;

  for (int i = tid; i < 64*32; i += 256) {
    int r = i >> 5, c4 = (i & 31) * 4;
    *(float4*)&As[r*132 + c4] = *(const float4*)&Ap[(size_t)(q0+r)*Dh + c4];
  }
  for (int i = tid; i < 128*32; i += 256) {
    int c = i >> 5, d4 = (i & 31) * 4;
    float4 v = *(const float4*)&up_w[(size_t)(c0+c)*Dh + d4];
    Ws[(d4+0)*132 + c] = v.x;
    Ws[(d4+1)*132 + c] = v.y;
    Ws[(d4+2)*132 + c] = v.z;
    Ws[(d4+3)*132 + c] = v.w;
  }
  __syncthreads();

  ull acc2[4][4];
  #pragma unroll
  for (int i = 0; i < 4; i++)
    #pragma unroll
    for (int j = 0; j < 4; j++) acc2[i][j] = 0ull;

  #pragma unroll 2
  for (int d4 = 0; d4 < 32; d4++) {
    ull wv2[4][4];
    #pragma unroll
    for (int j = 0; j < 4; j++) {
      ulonglong2 a = *(const ulonglong2*)&Ws[(d4*4+j)*132 + tx*8];
      ulonglong2 c = *(const ulonglong2*)&Ws[(d4*4+j)*132 + tx*8 + 4];
      wv2[j][0]=a.x; wv2[j][1]=a.y; wv2[j][2]=c.x; wv2[j][3]=c.y;
    }
    #pragma unroll
    for (int qq = 0; qq < 4; qq++) {
      float4 t = *(const float4*)&As[(ty*4+qq)*132 + d4*4];
      float av[4] = {t.x, t.y, t.z, t.w};
      #pragma unroll
      for (int j = 0; j < 4; j++) {
        ull ad = dup2(av[j]);
        #pragma unroll
        for (int p = 0; p < 4; p++) fma2(acc2[qq][p], ad, wv2[j][p]);
      }
    }
  }

  float acc[4][8];
  #pragma unroll
  for (int qq = 0; qq < 4; qq++)
    #pragma unroll
    for (int p = 0; p < 4; p++)
      unpack2(acc2[qq][p], acc[qq][2*p], acc[qq][2*p+1]);

  #pragma unroll
  for (int cc = 0; cc < 8; cc++) {
    int c = c0 + tx*8 + cc;
    float bb = up_b[c];
    *(float4*)&Yp[(size_t)c*HW + q0 + ty*4] =
      make_float4(acc[0][cc]+bb, acc[1][cc]+bb, acc[2][cc]+bb, acc[3][cc]+bb);
  }
}

// ======================= BN stats (per side, per channel) =======================
__global__ __launch_bounds__(256) void bn_stats_kernel()
{
  const int c = blockIdx.x, side = blockIdx.y;
  float s = 0.f, s2 = 0.f;
  for (int b = 0; b < NB; b++) {
    const float* p = d_y + (size_t)((side*NB + b)*Cc + c)*HW;
    for (int i = threadIdx.x; i < HW; i += 256) {
      float v = p[i];
      s += v; s2 += v*v;
    }
  }
  __shared__ float red[64];
  #pragma unroll
  for (int off = 16; off; off >>= 1) {
    s  += __shfl_down_sync(0xffffffffu, s,  off);
    s2 += __shfl_down_sync(0xffffffffu, s2, off);
  }
  int w = threadIdx.x >> 5;
  if ((threadIdx.x & 31) == 0) { red[w] = s; red[w + 32] = s2; }
  __syncthreads();
  if (threadIdx.x == 0) {
    float ts = 0.f, ts2 = 0.f;
    #pragma unroll
    for (int i = 0; i < 8; i++) { ts += red[i]; ts2 += red[i + 32]; }
    float mean = ts * (1.0f/16384.0f);
    float var  = ts2 * (1.0f/16384.0f) - mean*mean;
    d_bn[side*Cc + c] = make_float2(mean, rsqrtf(var + 1e-5f));
  }
}

// ======================= final: residual + BN apply =======================
__global__ __launch_bounds__(256) void final_kernel(
    const float* __restrict__ left, const float* __restrict__ right,
    const float* __restrict__ gamma, const float* __restrict__ beta,
    float* __restrict__ out)
{
  size_t i = ((size_t)blockIdx.x*256 + threadIdx.x) * 4;
  int q = (int)(i & 4095);
  size_t t = i >> 12;
  int c = (int)(t & 255); t >>= 8;
  int b = (int)(t & 3);
  int side = (int)(t >> 2);
  const float* x = side ? right : left;
  float4 xv = *(const float4*)&x[(((size_t)b*Cc + c) << 12) + q];
  float4 yv = *(const float4*)&d_y[i];
  float2 st = d_bn[side*Cc + c];
  float ga = gamma[c]*st.y;
  float be = beta[c] - ga*st.x;
  float4 r;
  r.x = xv.x + yv.x*ga + be;
  r.y = xv.y + yv.y*ga + be;
  r.z = xv.z + yv.z*ga + be;
  r.w = xv.w + yv.w*ga + be;
  *(float4*)&out[i] = r;
}

// ======================= launch =======================
extern "C" void kernel_launch(void* const* d_in, const int* in_sizes, int n_in,
                              void* d_out, int out_size)
{
  const float* left    = (const float*)d_in[0];
  const float* right   = (const float*)d_in[1];
  const float* pre_l   = (const float*)d_in[2];
  const float* pre_r   = (const float*)d_in[3];
  const float* query_l = (const float*)d_in[4];
  const float* key_l   = (const float*)d_in[5];
  const float* query_r = (const float*)d_in[6];
  const float* key_r   = (const float*)d_in[7];
  const float* theta_w = (const float*)d_in[8];
  const float* theta_b = (const float*)d_in[9];
  const float* phi_w   = (const float*)d_in[10];
  const float* phi_b   = (const float*)d_in[11];
  const float* g_w     = (const float*)d_in[12];
  const float* g_b     = (const float*)d_in[13];
  const float* up_w    = (const float*)d_in[14];
  const float* up_b    = (const float*)d_in[15];
  const float* bn_g    = (const float*)d_in[16];
  const float* bn_b    = (const float*)d_in[17];
  float* out = (float*)d_out;

  const int PROJ_SMEM  = (64*68 + 64*132) * 4;            // 51200
  const int FLASH_SMEM = (64*132 + 128*68 + 64*132 + 64*68) * 4; // 119808
  const int UP_SMEM    = (64*132 + 128*132) * 4;          // 101376
  cudaFuncSetAttribute(proj_kernel,  cudaFuncAttributeMaxDynamicSharedMemorySize, PROJ_SMEM);
  cudaFuncSetAttribute(flash_kernel, cudaFuncAttributeMaxDynamicSharedMemorySize, FLASH_SMEM);
  cudaFuncSetAttribute(up_kernel,    cudaFuncAttributeMaxDynamicSharedMemorySize, UP_SMEM);

  proj_kernel<<<dim3(64, NB, 6), 256, PROJ_SMEM>>>(
      left, right, pre_l, pre_r, query_l, key_l, query_r, key_r,
      theta_w, theta_b, phi_w, phi_b, g_w, g_b);

  flash_kernel<<<dim3(64, NB, 2), 256, FLASH_SMEM>>>(out);

  up_kernel<<<dim3(64, NB, 4), 256, UP_SMEM>>>(up_w, up_b);

  bn_stats_kernel<<<dim3(Cc, 2), 256>>>();

  final_kernel<<<dim3(2*NB*Cc*HW/4/256), 256>>>(left, right, bn_g, bn_b, out);
}

// round 8
// speedup vs baseline: 2.1077x; 2.1077x over previous
#include <cuda_runtime.h>
#include <cstdint>
#include <cstddef>

#define HW   4096
#define Dh   128
#define Cc   256
#define NB   4
#define ST   136   // smem tile row stride in bf16 elems (272B)

// ======================= helpers =======================
__device__ __forceinline__ uint32_t smem_u32(const void* p) {
  uint32_t a;
  asm("{ .reg .u64 t; cvta.to.shared.u64 t, %1; cvt.u32.u64 %0, t; }" : "=r"(a) : "l"(p));
  return a;
}
__device__ __forceinline__ void ldm_x4(uint32_t a, uint32_t* r) {
  asm volatile("ldmatrix.sync.aligned.m8n8.x4.shared.b16 {%0,%1,%2,%3}, [%4];"
               : "=r"(r[0]), "=r"(r[1]), "=r"(r[2]), "=r"(r[3]) : "r"(a));
}
__device__ __forceinline__ void ldm_x4_t(uint32_t a, uint32_t* r) {
  asm volatile("ldmatrix.sync.aligned.m8n8.x4.trans.shared.b16 {%0,%1,%2,%3}, [%4];"
               : "=r"(r[0]), "=r"(r[1]), "=r"(r[2]), "=r"(r[3]) : "r"(a));
}
__device__ __forceinline__ void hmma(float* d, const uint32_t* a, const uint32_t* b) {
  asm volatile("mma.sync.aligned.m16n8k16.row.col.f32.bf16.bf16.f32 "
               "{%0,%1,%2,%3}, {%4,%5,%6,%7}, {%8,%9}, {%0,%1,%2,%3};"
               : "+f"(d[0]), "+f"(d[1]), "+f"(d[2]), "+f"(d[3])
               : "r"(a[0]), "r"(a[1]), "r"(a[2]), "r"(a[3]), "r"(b[0]), "r"(b[1]));
}

// bf16 RN-even bits (kept in HIGH half, low 16 zero) — pure int ops, no CVT
__device__ __forceinline__ uint32_t hbits(float x) {
  uint32_t u = __float_as_uint(x);
  return (u + 0x7FFFu + ((u >> 16) & 1u)) & 0xFFFF0000u;
}
// fast exp on FMA/ALU pipes (no MUFU): exp(x) = 2^(x*log2e), rel err ~2e-6
__device__ __forceinline__ float fexp(float x) {
  float t = x * 1.4426950408889634f;
  float r = t + 12582912.0f;                 // round-to-nearest via magic
  int   n = __float_as_int(r) - 0x4B400000;  // integer part
  float f = t - (r - 12582912.0f);           // frac in [-0.5, 0.5]
  float p = 1.540353e-4f;
  p = fmaf(p, f, 1.3333558e-3f);
  p = fmaf(p, f, 9.6181291e-3f);
  p = fmaf(p, f, 5.5504109e-2f);
  p = fmaf(p, f, 2.4022651e-1f);
  p = fmaf(p, f, 6.9314718e-1f);
  p = fmaf(p, f, 1.0f);
  n = max(n, -126);
  return p * __int_as_float((n + 127) << 23);
}
// split 8 floats -> bf16 hi/lo packed stores
__device__ __forceinline__ void split8_store(const float* v, unsigned short* hiP,
                                             unsigned short* loP) {
  uint32_t hw[4], lw[4];
  #pragma unroll
  for (int i = 0; i < 4; i++) {
    uint32_t h0 = hbits(v[2*i]), h1 = hbits(v[2*i+1]);
    hw[i] = (h0 >> 16) | h1;
    float l0 = v[2*i]   - __uint_as_float(h0);
    float l1 = v[2*i+1] - __uint_as_float(h1);
    uint32_t g0 = hbits(l0), g1 = hbits(l1);
    lw[i] = (g0 >> 16) | g1;
  }
  *(uint4*)hiP = make_uint4(hw[0], hw[1], hw[2], hw[3]);
  *(uint4*)loP = make_uint4(lw[0], lw[1], lw[2], lw[3]);
}

// ---------------- scratch (device globals, no allocation) ----------------
__device__ unsigned short d_th_hi[(size_t)8*HW*Dh];  // theta [sb][q][d]
__device__ unsigned short d_th_lo[(size_t)8*HW*Dh];
__device__ unsigned short d_ph_hi[(size_t)8*HW*Dh];  // phi   [sb][key][d]
__device__ unsigned short d_ph_lo[(size_t)8*HW*Dh];
__device__ unsigned short d_g_hi [(size_t)8*HW*Dh];  // g     [sb][k][d]
__device__ unsigned short d_g_lo [(size_t)8*HW*Dh];
__device__ unsigned short d_P_hi [(size_t)8*HW*HW];  // exp(S) [sb][q][key]
__device__ unsigned short d_P_lo [(size_t)8*HW*HW];
__device__ float2 d_lc  [8*HW];                      // (l, c) per [sb][q]
__device__ float  d_after[(size_t)8*HW*Dh];
__device__ float  d_y    [(size_t)8*Cc*HW];
__device__ float2 d_bn   [2*Cc];

// ======================= zero l/c accumulators =======================
__global__ __launch_bounds__(256) void zero_lc_kernel() {
  int i = blockIdx.x*256 + threadIdx.x;
  if (i < 8*HW) d_lc[i] = make_float2(0.f, 0.f);
}

// ======================= projection (theta/phi/g) =======================
// grid (64 qtiles, B, 6), 256 threads, smem 51200B
__global__ __launch_bounds__(256) void proj_kernel(
    const float* __restrict__ left,   const float* __restrict__ right,
    const float* __restrict__ pre_l,  const float* __restrict__ pre_r,
    const float* __restrict__ query_l,const float* __restrict__ key_l,
    const float* __restrict__ query_r,const float* __restrict__ key_r,
    const float* __restrict__ theta_w,const float* __restrict__ theta_b,
    const float* __restrict__ phi_w,  const float* __restrict__ phi_b,
    const float* __restrict__ g_w,    const float* __restrict__ g_b)
{
  extern __shared__ float sm[];
  float* Xs = sm;            // [64 c][68]
  float* Wt = sm + 64*68;    // [64 c][132]

  const int qt = blockIdx.x, b = blockIdx.y, z = blockIdx.z;
  const int side = z / 3, proj = z - side*3;

  const float* src; const float* w; const float* bias; int cin;
  if (proj == 0)      { src = side ? right : left;  w = theta_w; bias = theta_b; cin = 257; }
  else if (proj == 1) { src = side ? left  : right; w = phi_w;   bias = phi_b;   cin = 256; }
  else                { src = side ? left  : right; w = g_w;     bias = g_b;     cin = 256; }

  const int tid = threadIdx.x, tx = tid & 15, ty = tid >> 4;
  const int q0 = qt * 64;
  const float* xb = src + (size_t)b * Cc * HW;

  float acc[4][8];
  #pragma unroll
  for (int i = 0; i < 4; i++)
    #pragma unroll
    for (int j = 0; j < 8; j++) acc[i][j] = 0.f;

  for (int c0 = 0; c0 < 256; c0 += 64) {
    __syncthreads();
    for (int i = tid; i < 64*16; i += 256) {
      int r = i >> 4, c4 = (i & 15) * 4;
      *(float4*)&Xs[r*68 + c4] = *(const float4*)&xb[(size_t)(c0 + r)*HW + q0 + c4];
    }
    for (int i = tid; i < 128*64; i += 256) {
      int d = i >> 6, c = i & 63;
      Wt[c*132 + d] = w[d*cin + c0 + c];
    }
    __syncthreads();
    #pragma unroll 4
    for (int c = 0; c < 64; c++) {
      float4 q4 = *(const float4*)&Xs[c*68 + ty*4];
      float4 w0 = *(const float4*)&Wt[c*132 + tx*8];
      float4 w1 = *(const float4*)&Wt[c*132 + tx*8 + 4];
      float qv[4] = {q4.x, q4.y, q4.z, q4.w};
      float wv[8] = {w0.x,w0.y,w0.z,w0.w, w1.x,w1.y,w1.z,w1.w};
      #pragma unroll
      for (int qq = 0; qq < 4; qq++)
        #pragma unroll
        for (int dd = 0; dd < 8; dd++)
          acc[qq][dd] += qv[qq]*wv[dd];
    }
  }

  const int d0 = tx*8;
  const int sb = side*NB + b;

  if (proj == 0) {
    const float* pre = side ? pre_r : pre_l;
    const float* qry = side ? query_r : query_l;
    #pragma unroll
    for (int qq = 0; qq < 4; qq++) {
      int q = q0 + ty*4 + qq;
      float prev = pre[(size_t)b*HW + q] * (1.0f/128.0f);
      float outv[8];
      #pragma unroll
      for (int dd = 0; dd < 8; dd++) {
        int d = d0 + dd;
        outv[dd] = acc[qq][dd] + bias[d] + w[d*257 + 256]*prev
                 + qry[((size_t)b*Dh + d)*HW + q];
      }
      size_t o = ((size_t)sb*HW + q)*Dh + d0;
      split8_store(outv, &d_th_hi[o], &d_th_lo[o]);
    }
  } else if (proj == 1) {
    const float* kf = side ? key_l : key_r;
    #pragma unroll
    for (int qq = 0; qq < 4; qq++) {
      int q = q0 + ty*4 + qq;
      float outv[8];
      #pragma unroll
      for (int dd = 0; dd < 8; dd++) {
        int d = d0 + dd;
        outv[dd] = acc[qq][dd] + bias[d] + kf[((size_t)b*Dh + d)*HW + q];
      }
      size_t o = ((size_t)sb*HW + q)*Dh + d0;
      split8_store(outv, &d_ph_hi[o], &d_ph_lo[o]);
    }
  } else {
    #pragma unroll
    for (int qq = 0; qq < 4; qq++) {
      int q = q0 + ty*4 + qq;
      float outv[8];
      #pragma unroll
      for (int dd = 0; dd < 8; dd++) outv[dd] = acc[qq][dd] + bias[d0+dd];
      size_t o = ((size_t)sb*HW + q)*Dh + d0;
      split8_store(outv, &d_g_hi[o], &d_g_lo[o]);
    }
  }
}

// ======================= GEMM-S: P = exp(theta phi^T), + l/c row sums ==========
// grid (32 ntiles, 32 mtiles, 8 sb), 256 threads, smem 139264B
#define TILE_BYTES (128*ST*2)   // 34816
#define S_SMEM (4*TILE_BYTES)

__global__ __launch_bounds__(256) void gemmS_kernel()
{
  extern __shared__ char smem[];
  const uint32_t sb32 = smem_u32(smem);
  const int ntile = blockIdx.x, mtile = blockIdx.y, sb = blockIdx.z;
  const int tid = threadIdx.x, wid = tid >> 5, lid = tid & 31;
  const int q0 = mtile*128, n0 = ntile*128;
  const uint32_t A_HI = 0, A_LO = TILE_BYTES, B_HI = 2*TILE_BYTES, B_LO = 3*TILE_BYTES;

  {
    const unsigned short* aH = d_th_hi + ((size_t)sb*HW + q0)*Dh;
    const unsigned short* aL = d_th_lo + ((size_t)sb*HW + q0)*Dh;
    const unsigned short* bH = d_ph_hi + ((size_t)sb*HW + n0)*Dh;
    const unsigned short* bL = d_ph_lo + ((size_t)sb*HW + n0)*Dh;
    for (int i = tid; i < 128*16; i += 256) {
      int r = i >> 4, c8 = (i & 15) * 8;
      uint32_t o = ((uint32_t)r*ST + c8) * 2;
      size_t go = (size_t)r*Dh + c8;
      *(uint4*)(smem + A_HI + o) = *(const uint4*)&aH[go];
      *(uint4*)(smem + A_LO + o) = *(const uint4*)&aL[go];
      *(uint4*)(smem + B_HI + o) = *(const uint4*)&bH[go];
      *(uint4*)(smem + B_LO + o) = *(const uint4*)&bL[go];
    }
  }
  __syncthreads();

  const int warpM = (wid & 3)*32, warpN = (wid >> 2)*64;
  float acc[2][8][4];
  #pragma unroll
  for (int mf = 0; mf < 2; mf++)
    #pragma unroll
    for (int nf = 0; nf < 8; nf++)
      #pragma unroll
      for (int e = 0; e < 4; e++) acc[mf][nf][e] = 0.f;

  const int arow = lid & 15;
  const int akh  = (lid & 16) ? 8 : 0;
  const int brow = (lid & 7) + ((lid & 16) ? 8 : 0);
  const int bkh  = (lid & 8) ? 8 : 0;

  const uint32_t aBase[3] = {sb32 + A_HI, sb32 + A_HI, sb32 + A_LO};
  const uint32_t bBase[3] = {sb32 + B_HI, sb32 + B_LO, sb32 + B_HI};

  #pragma unroll 1
  for (int t = 0; t < 3; t++) {
    const uint32_t aB = aBase[t], bB = bBase[t];
    #pragma unroll
    for (int k16 = 0; k16 < 8; k16++) {
      uint32_t af[2][4], bf[4][4];
      #pragma unroll
      for (int mf = 0; mf < 2; mf++)
        ldm_x4(aB + ((warpM + mf*16 + arow)*ST + k16*16 + akh)*2, af[mf]);
      #pragma unroll
      for (int nb = 0; nb < 4; nb++)
        ldm_x4(bB + ((warpN + nb*16 + brow)*ST + k16*16 + bkh)*2, bf[nb]);
      #pragma unroll
      for (int mf = 0; mf < 2; mf++)
        #pragma unroll
        for (int nf = 0; nf < 8; nf++)
          hmma(acc[mf][nf], af[mf], &bf[nf >> 1][(nf & 1)*2]);
    }
  }

  // epilogue: exp, split-store P, accumulate l/c row sums
  float ls[2][2] = {{0,0},{0,0}}, cs[2][2] = {{0,0},{0,0}};
  const int colb = warpN + (lid & 3)*2;
  #pragma unroll
  for (int mf = 0; mf < 2; mf++) {
    const int r0 = q0 + warpM + mf*16 + (lid >> 2);
    #pragma unroll
    for (int nf = 0; nf < 8; nf++) {
      float p0 = fexp(acc[mf][nf][0]), p1 = fexp(acc[mf][nf][1]);
      float p2 = fexp(acc[mf][nf][2]), p3 = fexp(acc[mf][nf][3]);
      const int col = colb + nf*8;
      ls[mf][0] += p0 + p1;  cs[mf][0] += p0*(float)col + p1*(float)(col+1);
      ls[mf][1] += p2 + p3;  cs[mf][1] += p2*(float)col + p3*(float)(col+1);

      uint32_t h0 = hbits(p0), h1 = hbits(p1), h2 = hbits(p2), h3 = hbits(p3);
      uint32_t g0 = hbits(p0 - __uint_as_float(h0));
      uint32_t g1 = hbits(p1 - __uint_as_float(h1));
      uint32_t g2 = hbits(p2 - __uint_as_float(h2));
      uint32_t g3 = hbits(p3 - __uint_as_float(h3));
      size_t base0 = ((size_t)sb*HW + r0)*HW + n0 + col;
      size_t base1 = base0 + (size_t)8*HW;
      *(uint32_t*)&d_P_hi[base0] = (h0 >> 16) | h1;
      *(uint32_t*)&d_P_lo[base0] = (g0 >> 16) | g1;
      *(uint32_t*)&d_P_hi[base1] = (h2 >> 16) | h3;
      *(uint32_t*)&d_P_lo[base1] = (g2 >> 16) | g3;
    }
  }
  #pragma unroll
  for (int mf = 0; mf < 2; mf++)
    #pragma unroll
    for (int h = 0; h < 2; h++) {
      float l = ls[mf][h], c = cs[mf][h];
      l += __shfl_xor_sync(0xffffffffu, l, 1);
      c += __shfl_xor_sync(0xffffffffu, c, 1);
      l += __shfl_xor_sync(0xffffffffu, l, 2);
      c += __shfl_xor_sync(0xffffffffu, c, 2);
      if ((lid & 3) == 0) {
        int r = q0 + warpM + mf*16 + (lid >> 2) + h*8;
        atomicAdd(&d_lc[sb*HW + r].x, l);
        atomicAdd(&d_lc[sb*HW + r].y, c);
      }
    }
}

// ======================= GEMM-PV: after = (P g)/l, index out ====================
// grid (32 mtiles, 8 sb), 256 threads, smem 139264B
__global__ __launch_bounds__(256) void gemmPV_kernel(float* __restrict__ out)
{
  extern __shared__ char smem[];
  const uint32_t sb32 = smem_u32(smem);
  const int mtile = blockIdx.x, sb = blockIdx.y;
  const int tid = threadIdx.x, wid = tid >> 5, lid = tid & 31;
  const int q0 = mtile*128;
  const uint32_t A_HI = 0, A_LO = TILE_BYTES, B_HI = 2*TILE_BYTES, B_LO = 3*TILE_BYTES;

  const int warpM = (wid & 3)*32, warpN = (wid >> 2)*64;
  float acc[2][8][4];
  #pragma unroll
  for (int mf = 0; mf < 2; mf++)
    #pragma unroll
    for (int nf = 0; nf < 8; nf++)
      #pragma unroll
      for (int e = 0; e < 4; e++) acc[mf][nf][e] = 0.f;

  const int arow = lid & 15;
  const int akh  = (lid & 16) ? 8 : 0;
  const int trow = lid & 15;                 // trans-B: k row
  const int tnh  = (lid & 16) ? 8 : 0;       // trans-B: n col offset

  const uint32_t aBase[3] = {sb32 + A_HI, sb32 + A_HI, sb32 + A_LO};
  const uint32_t bBase[3] = {sb32 + B_HI, sb32 + B_LO, sb32 + B_HI};

  #pragma unroll 1
  for (int ch = 0; ch < 32; ch++) {
    const int k0 = ch*128;
    __syncthreads();
    {
      const unsigned short* aH = d_P_hi + ((size_t)sb*HW + q0)*HW + k0;
      const unsigned short* aL = d_P_lo + ((size_t)sb*HW + q0)*HW + k0;
      const unsigned short* bH = d_g_hi + ((size_t)sb*HW + k0)*Dh;
      const unsigned short* bL = d_g_lo + ((size_t)sb*HW + k0)*Dh;
      for (int i = tid; i < 128*16; i += 256) {
        int r = i >> 4, c8 = (i & 15) * 8;
        uint32_t o = ((uint32_t)r*ST + c8) * 2;
        *(uint4*)(smem + A_HI + o) = *(const uint4*)&aH[(size_t)r*HW + c8];
        *(uint4*)(smem + A_LO + o) = *(const uint4*)&aL[(size_t)r*HW + c8];
        *(uint4*)(smem + B_HI + o) = *(const uint4*)&bH[(size_t)r*Dh + c8];
        *(uint4*)(smem + B_LO + o) = *(const uint4*)&bL[(size_t)r*Dh + c8];
      }
    }
    __syncthreads();

    #pragma unroll 1
    for (int t = 0; t < 3; t++) {
      const uint32_t aB = aBase[t], bB = bBase[t];
      #pragma unroll
      for (int k16 = 0; k16 < 8; k16++) {
        uint32_t af[2][4], bf[4][4];
        #pragma unroll
        for (int mf = 0; mf < 2; mf++)
          ldm_x4(aB + ((warpM + mf*16 + arow)*ST + k16*16 + akh)*2, af[mf]);
        #pragma unroll
        for (int nb = 0; nb < 4; nb++)
          ldm_x4_t(bB + ((k16*16 + trow)*ST + warpN + nb*16 + tnh)*2, bf[nb]);
        #pragma unroll
        for (int mf = 0; mf < 2; mf++)
          #pragma unroll
          for (int nf = 0; nf < 8; nf++)
            hmma(acc[mf][nf], af[mf], &bf[nf >> 1][(nf & 1)*2]);
      }
    }
  }

  // epilogue: normalize by l, write after + index
  #pragma unroll
  for (int mf = 0; mf < 2; mf++) {
    #pragma unroll
    for (int h = 0; h < 2; h++) {
      const int q = q0 + warpM + mf*16 + (lid >> 2) + h*8;
      float2 lc = d_lc[sb*HW + q];
      float inv = 1.0f / lc.x;
      float* dst = d_after + ((size_t)sb*HW + q)*Dh + warpN + (lid & 3)*2;
      #pragma unroll
      for (int nf = 0; nf < 8; nf++) {
        float2 v;
        v.x = acc[mf][nf][h*2 + 0] * inv;
        v.y = acc[mf][nf][h*2 + 1] * inv;
        *(float2*)&dst[nf*8] = v;
      }
      if (warpN == 0 && (lid & 3) == 0) {
        const int side = sb >> 2, b = sb & 3;
        out[(size_t)2*NB*Cc*HW + (size_t)side*NB*HW + (size_t)b*HW + q] =
            (float)(q & 127) - lc.y * inv;
      }
    }
  }
}

// ======================= up-projection =======================
__global__ __launch_bounds__(256) void up_kernel(
    const float* __restrict__ up_w, const float* __restrict__ up_b)
{
  extern __shared__ float sm[];
  float* As = sm;            // [64 q][132]
  float* Ws = sm + 64*132;   // [128 d][132]

  const int qt = blockIdx.x, b = blockIdx.y, z = blockIdx.z;
  const int side = z >> 1, ch = z & 1;
  const int sb = side*NB + b;
  const float* Ap = d_after + (size_t)sb*HW*Dh;
  float*       Yp = d_y     + (size_t)sb*Cc*HW;
  const int c0 = ch*128;
  const int tid = threadIdx.x, tx = tid & 15, ty = tid >> 4;
  const int q0 = qt*64;

  for (int i = tid; i < 64*32; i += 256) {
    int r = i >> 5, c4 = (i & 31) * 4;
    *(float4*)&As[r*132 + c4] = *(const float4*)&Ap[(size_t)(q0+r)*Dh + c4];
  }
  for (int i = tid; i < 128*32; i += 256) {
    int c = i >> 5, d4 = (i & 31) * 4;
    float4 v = *(const float4*)&up_w[(size_t)(c0+c)*Dh + d4];
    Ws[(d4+0)*132 + c] = v.x;
    Ws[(d4+1)*132 + c] = v.y;
    Ws[(d4+2)*132 + c] = v.z;
    Ws[(d4+3)*132 + c] = v.w;
  }
  __syncthreads();

  float acc[4][8];
  #pragma unroll
  for (int i = 0; i < 4; i++)
    #pragma unroll
    for (int j = 0; j < 8; j++) acc[i][j] = 0.f;

  #pragma unroll 2
  for (int d4 = 0; d4 < 32; d4++) {
    float wv[4][8];
    #pragma unroll
    for (int j = 0; j < 4; j++) {
      float4 a = *(const float4*)&Ws[(d4*4+j)*132 + tx*8];
      float4 c = *(const float4*)&Ws[(d4*4+j)*132 + tx*8 + 4];
      wv[j][0]=a.x; wv[j][1]=a.y; wv[j][2]=a.z; wv[j][3]=a.w;
      wv[j][4]=c.x; wv[j][5]=c.y; wv[j][6]=c.z; wv[j][7]=c.w;
    }
    #pragma unroll
    for (int qq = 0; qq < 4; qq++) {
      float4 t = *(const float4*)&As[(ty*4+qq)*132 + d4*4];
      float av[4] = {t.x, t.y, t.z, t.w};
      #pragma unroll
      for (int j = 0; j < 4; j++)
        #pragma unroll
        for (int cc = 0; cc < 8; cc++)
          acc[qq][cc] += av[j]*wv[j][cc];
    }
  }

  #pragma unroll
  for (int cc = 0; cc < 8; cc++) {
    int c = c0 + tx*8 + cc;
    float bb = up_b[c];
    *(float4*)&Yp[(size_t)c*HW + q0 + ty*4] =
      make_float4(acc[0][cc]+bb, acc[1][cc]+bb, acc[2][cc]+bb, acc[3][cc]+bb);
  }
}

// ======================= BN stats =======================
__global__ __launch_bounds__(256) void bn_stats_kernel()
{
  const int c = blockIdx.x, side = blockIdx.y;
  float s = 0.f, s2 = 0.f;
  for (int b = 0; b < NB; b++) {
    const float* p = d_y + (size_t)((side*NB + b)*Cc + c)*HW;
    for (int i = threadIdx.x; i < HW; i += 256) {
      float v = p[i];
      s += v; s2 += v*v;
    }
  }
  __shared__ float red[64];
  #pragma unroll
  for (int off = 16; off; off >>= 1) {
    s  += __shfl_down_sync(0xffffffffu, s,  off);
    s2 += __shfl_down_sync(0xffffffffu, s2, off);
  }
  int w = threadIdx.x >> 5;
  if ((threadIdx.x & 31) == 0) { red[w] = s; red[w + 32] = s2; }
  __syncthreads();
  if (threadIdx.x == 0) {
    float ts = 0.f, ts2 = 0.f;
    #pragma unroll
    for (int i = 0; i < 8; i++) { ts += red[i]; ts2 += red[i + 32]; }
    float mean = ts * (1.0f/16384.0f);
    float var  = ts2 * (1.0f/16384.0f) - mean*mean;
    d_bn[side*Cc + c] = make_float2(mean, rsqrtf(var + 1e-5f));
  }
}

// ======================= final: residual + BN apply =======================
__global__ __launch_bounds__(256) void final_kernel(
    const float* __restrict__ left, const float* __restrict__ right,
    const float* __restrict__ gamma, const float* __restrict__ beta,
    float* __restrict__ out)
{
  size_t i = ((size_t)blockIdx.x*256 + threadIdx.x) * 4;
  int q = (int)(i & 4095);
  size_t t = i >> 12;
  int c = (int)(t & 255); t >>= 8;
  int b = (int)(t & 3);
  int side = (int)(t >> 2);
  const float* x = side ? right : left;
  float4 xv = *(const float4*)&x[(((size_t)b*Cc + c) << 12) + q];
  float4 yv = *(const float4*)&d_y[i];
  float2 st = d_bn[side*Cc + c];
  float ga = gamma[c]*st.y;
  float be = beta[c] - ga*st.x;
  float4 r;
  r.x = xv.x + yv.x*ga + be;
  r.y = xv.y + yv.y*ga + be;
  r.z = xv.z + yv.z*ga + be;
  r.w = xv.w + yv.w*ga + be;
  *(float4*)&out[i] = r;
}

// ======================= launch =======================
extern "C" void kernel_launch(void* const* d_in, const int* in_sizes, int n_in,
                              void* d_out, int out_size)
{
  const float* left    = (const float*)d_in[0];
  const float* right   = (const float*)d_in[1];
  const float* pre_l   = (const float*)d_in[2];
  const float* pre_r   = (const float*)d_in[3];
  const float* query_l = (const float*)d_in[4];
  const float* key_l   = (const float*)d_in[5];
  const float* query_r = (const float*)d_in[6];
  const float* key_r   = (const float*)d_in[7];
  const float* theta_w = (const float*)d_in[8];
  const float* theta_b = (const float*)d_in[9];
  const float* phi_w   = (const float*)d_in[10];
  const float* phi_b   = (const float*)d_in[11];
  const float* g_w     = (const float*)d_in[12];
  const float* g_b     = (const float*)d_in[13];
  const float* up_w    = (const float*)d_in[14];
  const float* up_b    = (const float*)d_in[15];
  const float* bn_g    = (const float*)d_in[16];
  const float* bn_b    = (const float*)d_in[17];
  float* out = (float*)d_out;

  const int PROJ_SMEM = (64*68 + 64*132) * 4;
  const int UP_SMEM   = (64*132 + 128*132) * 4;
  cudaFuncSetAttribute(proj_kernel,   cudaFuncAttributeMaxDynamicSharedMemorySize, PROJ_SMEM);
  cudaFuncSetAttribute(gemmS_kernel,  cudaFuncAttributeMaxDynamicSharedMemorySize, S_SMEM);
  cudaFuncSetAttribute(gemmPV_kernel, cudaFuncAttributeMaxDynamicSharedMemorySize, S_SMEM);
  cudaFuncSetAttribute(up_kernel,     cudaFuncAttributeMaxDynamicSharedMemorySize, UP_SMEM);

  zero_lc_kernel<<<128, 256>>>();

  proj_kernel<<<dim3(64, NB, 6), 256, PROJ_SMEM>>>(
      left, right, pre_l, pre_r, query_l, key_l, query_r, key_r,
      theta_w, theta_b, phi_w, phi_b, g_w, g_b);

  gemmS_kernel<<<dim3(32, 32, 8), 256, S_SMEM>>>();

  gemmPV_kernel<<<dim3(32, 8), 256, S_SMEM>>>(out);

  up_kernel<<<dim3(64, NB, 4), 256, UP_SMEM>>>(up_w, up_b);

  bn_stats_kernel<<<dim3(Cc, 2), 256>>>();

  final_kernel<<<dim3(2*NB*Cc*HW/4/256), 256>>>(left, right, bn_g, bn_b, out);
}

// round 9
// speedup vs baseline: 3.1056x; 1.4735x over previous
#include <cuda_runtime.h>
#include <cstdint>
#include <cstddef>

#define HW   4096
#define Dh   128
#define Cc   256
#define NB   4
#define ST   136   // smem tile row stride in bf16 elems (272B, ldmatrix conflict-free)
#define BK   64    // key chunk per iteration
#define KSPLIT 4
#define NITER (HW/KSPLIT/BK)   // 16

// ======================= helpers =======================
__device__ __forceinline__ uint32_t smem_u32(const void* p) {
  uint32_t a;
  asm("{ .reg .u64 t; cvta.to.shared.u64 t, %1; cvt.u32.u64 %0, t; }" : "=r"(a) : "l"(p));
  return a;
}
__device__ __forceinline__ void ldm_x4(uint32_t a, uint32_t* r) {
  asm volatile("ldmatrix.sync.aligned.m8n8.x4.shared.b16 {%0,%1,%2,%3}, [%4];"
               : "=r"(r[0]), "=r"(r[1]), "=r"(r[2]), "=r"(r[3]) : "r"(a));
}
__device__ __forceinline__ void ldm_x4_t(uint32_t a, uint32_t* r) {
  asm volatile("ldmatrix.sync.aligned.m8n8.x4.trans.shared.b16 {%0,%1,%2,%3}, [%4];"
               : "=r"(r[0]), "=r"(r[1]), "=r"(r[2]), "=r"(r[3]) : "r"(a));
}
__device__ __forceinline__ void hmma(float* d, const uint32_t* a, const uint32_t* b) {
  asm volatile("mma.sync.aligned.m16n8k16.row.col.f32.bf16.bf16.f32 "
               "{%0,%1,%2,%3}, {%4,%5,%6,%7}, {%8,%9}, {%0,%1,%2,%3};"
               : "+f"(d[0]), "+f"(d[1]), "+f"(d[2]), "+f"(d[3])
               : "r"(a[0]), "r"(a[1]), "r"(a[2]), "r"(a[3]), "r"(b[0]), "r"(b[1]));
}
__device__ __forceinline__ void cpasync16(uint32_t dst, const void* src) {
  asm volatile("cp.async.cg.shared.global [%0], [%1], 16;" :: "r"(dst), "l"(src));
}
#define CP_COMMIT() asm volatile("cp.async.commit_group;" ::: "memory")
#define CP_WAIT1()  asm volatile("cp.async.wait_group 1;" ::: "memory")
#define CP_WAIT0()  asm volatile("cp.async.wait_group 0;" ::: "memory")

// bf16 RN-even bits (kept in HIGH half, low 16 zero) — pure int ops, no CVT
__device__ __forceinline__ uint32_t hbits(float x) {
  uint32_t u = __float_as_uint(x);
  return (u + 0x7FFFu + ((u >> 16) & 1u)) & 0xFFFF0000u;
}
// fast exp on FMA/ALU pipes (no MUFU)
__device__ __forceinline__ float fexp(float x) {
  float t = x * 1.4426950408889634f;
  float r = t + 12582912.0f;
  int   n = __float_as_int(r) - 0x4B400000;
  float f = t - (r - 12582912.0f);
  float p = 1.540353e-4f;
  p = fmaf(p, f, 1.3333558e-3f);
  p = fmaf(p, f, 9.6181291e-3f);
  p = fmaf(p, f, 5.5504109e-2f);
  p = fmaf(p, f, 2.4022651e-1f);
  p = fmaf(p, f, 6.9314718e-1f);
  p = fmaf(p, f, 1.0f);
  n = max(n, -126);
  return p * __int_as_float((n + 127) << 23);
}
// pack (x,y) -> bf16x2 hi and residual bf16x2 lo
__device__ __forceinline__ void packpair(float x, float y, uint32_t& h, uint32_t& l) {
  uint32_t hx = hbits(x), hy = hbits(y);
  h = (hx >> 16) | hy;
  float lx = x - __uint_as_float(hx), ly = y - __uint_as_float(hy);
  l = (hbits(lx) >> 16) | hbits(ly);
}
// split 8 floats -> bf16 hi/lo packed stores
__device__ __forceinline__ void split8_store(const float* v, unsigned short* hiP,
                                             unsigned short* loP) {
  uint32_t hw[4], lw[4];
  #pragma unroll
  for (int i = 0; i < 4; i++) {
    uint32_t h0 = hbits(v[2*i]), h1 = hbits(v[2*i+1]);
    hw[i] = (h0 >> 16) | h1;
    float l0 = v[2*i]   - __uint_as_float(h0);
    float l1 = v[2*i+1] - __uint_as_float(h1);
    uint32_t g0 = hbits(l0), g1 = hbits(l1);
    lw[i] = (g0 >> 16) | g1;
  }
  *(uint4*)hiP = make_uint4(hw[0], hw[1], hw[2], hw[3]);
  *(uint4*)loP = make_uint4(lw[0], lw[1], lw[2], lw[3]);
}

// ---------------- scratch (device globals, no allocation) ----------------
__device__ unsigned short d_th_hi[(size_t)8*HW*Dh];  // theta [sb][q][d]
__device__ unsigned short d_th_lo[(size_t)8*HW*Dh];
__device__ unsigned short d_ph_hi[(size_t)8*HW*Dh];  // phi   [sb][key][d]
__device__ unsigned short d_ph_lo[(size_t)8*HW*Dh];
__device__ unsigned short d_g_hi [(size_t)8*HW*Dh];  // g     [sb][k][d]
__device__ unsigned short d_g_lo [(size_t)8*HW*Dh];
__device__ float  d_op [(size_t)KSPLIT*8*HW*Dh];     // unnormalized O partials
__device__ float2 d_lcp[(size_t)KSPLIT*8*HW];        // (l, c) partials
__device__ float  d_after[(size_t)8*HW*Dh];
__device__ float  d_y    [(size_t)8*Cc*HW];
__device__ float2 d_bn   [2*Cc];

// ======================= projection (theta/phi/g) =======================
__global__ __launch_bounds__(256) void proj_kernel(
    const float* __restrict__ left,   const float* __restrict__ right,
    const float* __restrict__ pre_l,  const float* __restrict__ pre_r,
    const float* __restrict__ query_l,const float* __restrict__ key_l,
    const float* __restrict__ query_r,const float* __restrict__ key_r,
    const float* __restrict__ theta_w,const float* __restrict__ theta_b,
    const float* __restrict__ phi_w,  const float* __restrict__ phi_b,
    const float* __restrict__ g_w,    const float* __restrict__ g_b)
{
  extern __shared__ float sm[];
  float* Xs = sm;            // [64 c][68]
  float* Wt = sm + 64*68;    // [64 c][132]

  const int qt = blockIdx.x, b = blockIdx.y, z = blockIdx.z;
  const int side = z / 3, proj = z - side*3;

  const float* src; const float* w; const float* bias; int cin;
  if (proj == 0)      { src = side ? right : left;  w = theta_w; bias = theta_b; cin = 257; }
  else if (proj == 1) { src = side ? left  : right; w = phi_w;   bias = phi_b;   cin = 256; }
  else                { src = side ? left  : right; w = g_w;     bias = g_b;     cin = 256; }

  const int tid = threadIdx.x, tx = tid & 15, ty = tid >> 4;
  const int q0 = qt * 64;
  const float* xb = src + (size_t)b * Cc * HW;

  float acc[4][8];
  #pragma unroll
  for (int i = 0; i < 4; i++)
    #pragma unroll
    for (int j = 0; j < 8; j++) acc[i][j] = 0.f;

  for (int c0 = 0; c0 < 256; c0 += 64) {
    __syncthreads();
    for (int i = tid; i < 64*16; i += 256) {
      int r = i >> 4, c4 = (i & 15) * 4;
      *(float4*)&Xs[r*68 + c4] = *(const float4*)&xb[(size_t)(c0 + r)*HW + q0 + c4];
    }
    for (int i = tid; i < 128*64; i += 256) {
      int d = i >> 6, c = i & 63;
      Wt[c*132 + d] = w[d*cin + c0 + c];
    }
    __syncthreads();
    #pragma unroll 4
    for (int c = 0; c < 64; c++) {
      float4 q4 = *(const float4*)&Xs[c*68 + ty*4];
      float4 w0 = *(const float4*)&Wt[c*132 + tx*8];
      float4 w1 = *(const float4*)&Wt[c*132 + tx*8 + 4];
      float qv[4] = {q4.x, q4.y, q4.z, q4.w};
      float wv[8] = {w0.x,w0.y,w0.z,w0.w, w1.x,w1.y,w1.z,w1.w};
      #pragma unroll
      for (int qq = 0; qq < 4; qq++)
        #pragma unroll
        for (int dd = 0; dd < 8; dd++)
          acc[qq][dd] += qv[qq]*wv[dd];
    }
  }

  const int d0 = tx*8;
  const int sb = side*NB + b;

  if (proj == 0) {
    const float* pre = side ? pre_r : pre_l;
    const float* qry = side ? query_r : query_l;
    #pragma unroll
    for (int qq = 0; qq < 4; qq++) {
      int q = q0 + ty*4 + qq;
      float prev = pre[(size_t)b*HW + q] * (1.0f/128.0f);
      float outv[8];
      #pragma unroll
      for (int dd = 0; dd < 8; dd++) {
        int d = d0 + dd;
        outv[dd] = acc[qq][dd] + bias[d] + w[d*257 + 256]*prev
                 + qry[((size_t)b*Dh + d)*HW + q];
      }
      size_t o = ((size_t)sb*HW + q)*Dh + d0;
      split8_store(outv, &d_th_hi[o], &d_th_lo[o]);
    }
  } else if (proj == 1) {
    const float* kf = side ? key_l : key_r;
    #pragma unroll
    for (int qq = 0; qq < 4; qq++) {
      int q = q0 + ty*4 + qq;
      float outv[8];
      #pragma unroll
      for (int dd = 0; dd < 8; dd++) {
        int d = d0 + dd;
        outv[dd] = acc[qq][dd] + bias[d] + kf[((size_t)b*Dh + d)*HW + q];
      }
      size_t o = ((size_t)sb*HW + q)*Dh + d0;
      split8_store(outv, &d_ph_hi[o], &d_ph_lo[o]);
    }
  } else {
    #pragma unroll
    for (int qq = 0; qq < 4; qq++) {
      int q = q0 + ty*4 + qq;
      float outv[8];
      #pragma unroll
      for (int dd = 0; dd < 8; dd++) outv[dd] = acc[qq][dd] + bias[d0+dd];
      size_t o = ((size_t)sb*HW + q)*Dh + d0;
      split8_store(outv, &d_g_hi[o], &d_g_lo[o]);
    }
  }
}

// ======================= fused flash attention (HMMA, split-bf16) ===============
// grid (32 mtiles, KSPLIT, 8 sb), 256 threads, smem 208896B
#define TH_HI_OFF 0u
#define TH_LO_OFF 34816u
#define PHI_OFF   69632u     // + buf*34816, lo at +17408
#define G_OFF     139264u    // + buf*34816, lo at +17408
#define FL_SMEM   208896

__global__ __launch_bounds__(256, 1) void flash_kernel()
{
  extern __shared__ char smem[];
  const uint32_t sb32 = smem_u32(smem);
  const int mtile = blockIdx.x, split = blockIdx.y, sb = blockIdx.z;
  const int tid = threadIdx.x, wid = tid >> 5, lid = tid & 31;
  const int q0 = mtile * 128;
  const int kbase0 = split * (HW / KSPLIT);

  const unsigned short* thH = d_th_hi + ((size_t)sb*HW + q0)*Dh;
  const unsigned short* thL = d_th_lo + ((size_t)sb*HW + q0)*Dh;
  const unsigned short* phH = d_ph_hi + (size_t)sb*HW*Dh;
  const unsigned short* phL = d_ph_lo + (size_t)sb*HW*Dh;
  const unsigned short* gH  = d_g_hi  + (size_t)sb*HW*Dh;
  const unsigned short* gL  = d_g_lo  + (size_t)sb*HW*Dh;

  // theta resident load
  #pragma unroll
  for (int t = 0; t < 8; t++) {
    int i = tid + t*256;
    int r = i >> 4, c8 = (i & 15) * 8;
    uint32_t o = (uint32_t)(r*ST + c8) * 2;
    size_t go = (size_t)r*Dh + c8;
    *(uint4*)(smem + TH_HI_OFF + o) = *(const uint4*)&thH[go];
    *(uint4*)(smem + TH_LO_OFF + o) = *(const uint4*)&thL[go];
  }

  // issue chunk loader (phi + g rows [kb, kb+64))
  auto issue_chunk = [&](int buf, int kb) {
    uint32_t PB = sb32 + PHI_OFF + (uint32_t)buf*34816u;
    uint32_t GB = sb32 + G_OFF   + (uint32_t)buf*34816u;
    #pragma unroll
    for (int t = 0; t < 4; t++) {
      int i = tid + t*256;
      int r = i >> 4, c8 = (i & 15) * 8;
      uint32_t o = (uint32_t)(r*ST + c8) * 2;
      size_t go = (size_t)(kb + r)*Dh + c8;
      cpasync16(PB + o,          phH + go);
      cpasync16(PB + 17408u + o, phL + go);
      cpasync16(GB + o,          gH + go);
      cpasync16(GB + 17408u + o, gL + go);
    }
  };

  issue_chunk(0, kbase0);
  CP_COMMIT();

  const int m0   = wid * 16;
  const int arow = lid & 15;
  const int akh  = (lid & 16) ? 8 : 0;
  const int brow = (lid & 7) + ((lid & 16) ? 8 : 0);
  const int bkh  = (lid & 8) ? 8 : 0;
  const int trow = lid & 15;
  const int tnh  = (lid & 16) ? 8 : 0;

  float O[16][4];
  #pragma unroll
  for (int nf = 0; nf < 16; nf++)
    #pragma unroll
    for (int e = 0; e < 4; e++) O[nf][e] = 0.f;
  float lacc0 = 0.f, lacc1 = 0.f, cacc0 = 0.f, cacc1 = 0.f;

  #pragma unroll 1
  for (int it = 0; it < NITER; it++) {
    const int buf = it & 1;
    if (it + 1 < NITER) {
      issue_chunk(buf ^ 1, kbase0 + (it + 1)*BK);
      CP_COMMIT();
      CP_WAIT1();
    } else {
      CP_WAIT0();
    }
    __syncthreads();

    const uint32_t PH = sb32 + PHI_OFF + (uint32_t)buf*34816u;
    const uint32_t PL = PH + 17408u;
    const uint32_t GHs = sb32 + G_OFF + (uint32_t)buf*34816u;
    const uint32_t GLs = GHs + 17408u;

    // ---- S = theta phi^T (m16 x n64 per warp, 3 terms) ----
    float acc[8][4];
    #pragma unroll
    for (int nf = 0; nf < 8; nf++)
      #pragma unroll
      for (int e = 0; e < 4; e++) acc[nf][e] = 0.f;

    #pragma unroll
    for (int k16 = 0; k16 < 8; k16++) {
      uint32_t ah[4], al[4];
      ldm_x4(sb32 + TH_HI_OFF + ((m0 + arow)*ST + k16*16 + akh)*2, ah);
      ldm_x4(sb32 + TH_LO_OFF + ((m0 + arow)*ST + k16*16 + akh)*2, al);
      #pragma unroll
      for (int nb = 0; nb < 4; nb++) {
        uint32_t bh[4], bl[4];
        ldm_x4(PH + ((nb*16 + brow)*ST + k16*16 + bkh)*2, bh);
        hmma(acc[2*nb],   ah, bh);
        hmma(acc[2*nb+1], ah, bh + 2);
        hmma(acc[2*nb],   al, bh);
        hmma(acc[2*nb+1], al, bh + 2);
        ldm_x4(PL + ((nb*16 + brow)*ST + k16*16 + bkh)*2, bl);
        hmma(acc[2*nb],   ah, bl);
        hmma(acc[2*nb+1], ah, bl + 2);
      }
    }

    // ---- exp + l/c row sums ----
    const int kb = kbase0 + it*BK;
    #pragma unroll
    for (int nf = 0; nf < 8; nf++) {
      int key = kb + nf*8 + (lid & 3)*2;
      float w0 = (float)(key & 127), w1 = w0 + 1.0f;
      float p0 = fexp(acc[nf][0]), p1 = fexp(acc[nf][1]);
      float p2 = fexp(acc[nf][2]), p3 = fexp(acc[nf][3]);
      acc[nf][0] = p0; acc[nf][1] = p1; acc[nf][2] = p2; acc[nf][3] = p3;
      lacc0 += p0 + p1;               lacc1 += p2 + p3;
      cacc0 += p0*w0 + p1*w1;         cacc1 += p2*w0 + p3*w1;
    }

    // ---- O += P g  (register repack of P, m16 x d128 per warp, 3 terms) ----
    #pragma unroll
    for (int kk = 0; kk < 4; kk++) {
      uint32_t a_h[4], a_l[4];
      packpair(acc[2*kk][0],   acc[2*kk][1],   a_h[0], a_l[0]);
      packpair(acc[2*kk][2],   acc[2*kk][3],   a_h[1], a_l[1]);
      packpair(acc[2*kk+1][0], acc[2*kk+1][1], a_h[2], a_l[2]);
      packpair(acc[2*kk+1][2], acc[2*kk+1][3], a_h[3], a_l[3]);
      #pragma unroll
      for (int nb = 0; nb < 8; nb++) {
        uint32_t bh[4], bl[4];
        ldm_x4_t(GHs + ((kk*16 + trow)*ST + nb*16 + tnh)*2, bh);
        hmma(O[2*nb],   a_h, bh);
        hmma(O[2*nb+1], a_h, bh + 2);
        hmma(O[2*nb],   a_l, bh);
        hmma(O[2*nb+1], a_l, bh + 2);
        ldm_x4_t(GLs + ((kk*16 + trow)*ST + nb*16 + tnh)*2, bl);
        hmma(O[2*nb],   a_h, bl);
        hmma(O[2*nb+1], a_h, bl + 2);
      }
    }
    __syncthreads();
  }

  // quad-reduce l/c (cols within row live on lanes lid^1, lid^2)
  #pragma unroll
  for (int off = 1; off <= 2; off <<= 1) {
    lacc0 += __shfl_xor_sync(0xffffffffu, lacc0, off);
    lacc1 += __shfl_xor_sync(0xffffffffu, lacc1, off);
    cacc0 += __shfl_xor_sync(0xffffffffu, cacc0, off);
    cacc1 += __shfl_xor_sync(0xffffffffu, cacc1, off);
  }

  const int r0 = q0 + m0 + (lid >> 2);
  const int ssb = split*8 + sb;
  {
    float* o0 = d_op + ((size_t)ssb*HW + r0)*Dh + (lid & 3)*2;
    float* o1 = o0 + (size_t)8*Dh;
    #pragma unroll
    for (int nf = 0; nf < 16; nf++) {
      *(float2*)&o0[nf*8] = make_float2(O[nf][0], O[nf][1]);
      *(float2*)&o1[nf*8] = make_float2(O[nf][2], O[nf][3]);
    }
  }
  if ((lid & 3) == 0) {
    d_lcp[(size_t)ssb*HW + r0]     = make_float2(lacc0, cacc0);
    d_lcp[(size_t)ssb*HW + r0 + 8] = make_float2(lacc1, cacc1);
  }
}

// ======================= combine partials: normalize, index out =================
// grid (4096, 8), 128 threads
__global__ __launch_bounds__(128) void combine_kernel(float* __restrict__ out)
{
  const int q = blockIdx.x, sb = blockIdx.y, d = threadIdx.x;
  float l = 0.f, c = 0.f;
  #pragma unroll
  for (int s = 0; s < KSPLIT; s++) {
    float2 lc = d_lcp[(size_t)(s*8 + sb)*HW + q];
    l += lc.x; c += lc.y;
  }
  float o = 0.f;
  #pragma unroll
  for (int s = 0; s < KSPLIT; s++)
    o += d_op[((size_t)(s*8 + sb)*HW + q)*Dh + d];
  float inv = 1.0f / l;
  d_after[((size_t)sb*HW + q)*Dh + d] = o * inv;
  if (d == 0)
    out[(size_t)2*NB*Cc*HW + (size_t)sb*HW + q] = (float)(q & 127) - c * inv;
}

// ======================= up-projection =======================
__global__ __launch_bounds__(256) void up_kernel(
    const float* __restrict__ up_w, const float* __restrict__ up_b)
{
  extern __shared__ float sm[];
  float* As = sm;            // [64 q][132]
  float* Ws = sm + 64*132;   // [128 d][132]

  const int qt = blockIdx.x, b = blockIdx.y, z = blockIdx.z;
  const int side = z >> 1, ch = z & 1;
  const int sb = side*NB + b;
  const float* Ap = d_after + (size_t)sb*HW*Dh;
  float*       Yp = d_y     + (size_t)sb*Cc*HW;
  const int c0 = ch*128;
  const int tid = threadIdx.x, tx = tid & 15, ty = tid >> 4;
  const int q0 = qt*64;

  for (int i = tid; i < 64*32; i += 256) {
    int r = i >> 5, c4 = (i & 31) * 4;
    *(float4*)&As[r*132 + c4] = *(const float4*)&Ap[(size_t)(q0+r)*Dh + c4];
  }
  for (int i = tid; i < 128*32; i += 256) {
    int c = i >> 5, d4 = (i & 31) * 4;
    float4 v = *(const float4*)&up_w[(size_t)(c0+c)*Dh + d4];
    Ws[(d4+0)*132 + c] = v.x;
    Ws[(d4+1)*132 + c] = v.y;
    Ws[(d4+2)*132 + c] = v.z;
    Ws[(d4+3)*132 + c] = v.w;
  }
  __syncthreads();

  float acc[4][8];
  #pragma unroll
  for (int i = 0; i < 4; i++)
    #pragma unroll
    for (int j = 0; j < 8; j++) acc[i][j] = 0.f;

  #pragma unroll 2
  for (int d4 = 0; d4 < 32; d4++) {
    float wv[4][8];
    #pragma unroll
    for (int j = 0; j < 4; j++) {
      float4 a = *(const float4*)&Ws[(d4*4+j)*132 + tx*8];
      float4 c = *(const float4*)&Ws[(d4*4+j)*132 + tx*8 + 4];
      wv[j][0]=a.x; wv[j][1]=a.y; wv[j][2]=a.z; wv[j][3]=a.w;
      wv[j][4]=c.x; wv[j][5]=c.y; wv[j][6]=c.z; wv[j][7]=c.w;
    }
    #pragma unroll
    for (int qq = 0; qq < 4; qq++) {
      float4 t = *(const float4*)&As[(ty*4+qq)*132 + d4*4];
      float av[4] = {t.x, t.y, t.z, t.w};
      #pragma unroll
      for (int j = 0; j < 4; j++)
        #pragma unroll
        for (int cc = 0; cc < 8; cc++)
          acc[qq][cc] += av[j]*wv[j][cc];
    }
  }

  #pragma unroll
  for (int cc = 0; cc < 8; cc++) {
    int c = c0 + tx*8 + cc;
    float bb = up_b[c];
    *(float4*)&Yp[(size_t)c*HW + q0 + ty*4] =
      make_float4(acc[0][cc]+bb, acc[1][cc]+bb, acc[2][cc]+bb, acc[3][cc]+bb);
  }
}

// ======================= BN stats =======================
__global__ __launch_bounds__(256) void bn_stats_kernel()
{
  const int c = blockIdx.x, side = blockIdx.y;
  float s = 0.f, s2 = 0.f;
  for (int b = 0; b < NB; b++) {
    const float* p = d_y + (size_t)((side*NB + b)*Cc + c)*HW;
    for (int i = threadIdx.x; i < HW; i += 256) {
      float v = p[i];
      s += v; s2 += v*v;
    }
  }
  __shared__ float red[64];
  #pragma unroll
  for (int off = 16; off; off >>= 1) {
    s  += __shfl_down_sync(0xffffffffu, s,  off);
    s2 += __shfl_down_sync(0xffffffffu, s2, off);
  }
  int w = threadIdx.x >> 5;
  if ((threadIdx.x & 31) == 0) { red[w] = s; red[w + 32] = s2; }
  __syncthreads();
  if (threadIdx.x == 0) {
    float ts = 0.f, ts2 = 0.f;
    #pragma unroll
    for (int i = 0; i < 8; i++) { ts += red[i]; ts2 += red[i + 32]; }
    float mean = ts * (1.0f/16384.0f);
    float var  = ts2 * (1.0f/16384.0f) - mean*mean;
    d_bn[side*Cc + c] = make_float2(mean, rsqrtf(var + 1e-5f));
  }
}

// ======================= final: residual + BN apply =======================
__global__ __launch_bounds__(256) void final_kernel(
    const float* __restrict__ left, const float* __restrict__ right,
    const float* __restrict__ gamma, const float* __restrict__ beta,
    float* __restrict__ out)
{
  size_t i = ((size_t)blockIdx.x*256 + threadIdx.x) * 4;
  int q = (int)(i & 4095);
  size_t t = i >> 12;
  int c = (int)(t & 255); t >>= 8;
  int b = (int)(t & 3);
  int side = (int)(t >> 2);
  const float* x = side ? right : left;
  float4 xv = *(const float4*)&x[(((size_t)b*Cc + c) << 12) + q];
  float4 yv = *(const float4*)&d_y[i];
  float2 st = d_bn[side*Cc + c];
  float ga = gamma[c]*st.y;
  float be = beta[c] - ga*st.x;
  float4 r;
  r.x = xv.x + yv.x*ga + be;
  r.y = xv.y + yv.y*ga + be;
  r.z = xv.z + yv.z*ga + be;
  r.w = xv.w + yv.w*ga + be;
  *(float4*)&out[i] = r;
}

// ======================= launch =======================
extern "C" void kernel_launch(void* const* d_in, const int* in_sizes, int n_in,
                              void* d_out, int out_size)
{
  const float* left    = (const float*)d_in[0];
  const float* right   = (const float*)d_in[1];
  const float* pre_l   = (const float*)d_in[2];
  const float* pre_r   = (const float*)d_in[3];
  const float* query_l = (const float*)d_in[4];
  const float* key_l   = (const float*)d_in[5];
  const float* query_r = (const float*)d_in[6];
  const float* key_r   = (const float*)d_in[7];
  const float* theta_w = (const float*)d_in[8];
  const float* theta_b = (const float*)d_in[9];
  const float* phi_w   = (const float*)d_in[10];
  const float* phi_b   = (const float*)d_in[11];
  const float* g_w     = (const float*)d_in[12];
  const float* g_b     = (const float*)d_in[13];
  const float* up_w    = (const float*)d_in[14];
  const float* up_b    = (const float*)d_in[15];
  const float* bn_g    = (const float*)d_in[16];
  const float* bn_b    = (const float*)d_in[17];
  float* out = (float*)d_out;

  const int PROJ_SMEM = (64*68 + 64*132) * 4;
  const int UP_SMEM   = (64*132 + 128*132) * 4;
  cudaFuncSetAttribute(proj_kernel,  cudaFuncAttributeMaxDynamicSharedMemorySize, PROJ_SMEM);
  cudaFuncSetAttribute(flash_kernel, cudaFuncAttributeMaxDynamicSharedMemorySize, FL_SMEM);
  cudaFuncSetAttribute(up_kernel,    cudaFuncAttributeMaxDynamicSharedMemorySize, UP_SMEM);

  proj_kernel<<<dim3(64, NB, 6), 256, PROJ_SMEM>>>(
      left, right, pre_l, pre_r, query_l, key_l, query_r, key_r,
      theta_w, theta_b, phi_w, phi_b, g_w, g_b);

  flash_kernel<<<dim3(32, KSPLIT, 8), 256, FL_SMEM>>>();

  combine_kernel<<<dim3(HW, 8), 128>>>(out);

  up_kernel<<<dim3(64, NB, 4), 256, UP_SMEM>>>(up_w, up_b);

  bn_stats_kernel<<<dim3(Cc, 2), 256>>>();

  final_kernel<<<dim3(2*NB*Cc*HW/4/256), 256>>>(left, right, bn_g, bn_b, out);
}